// round 11
// baseline (speedup 1.0000x reference)
#include <cuda_runtime.h>
#include <cuda_fp16.h>
#include <cstdint>

#define N_R   100000
#define N_E   1200000
#define G_N   4096
#define H     64
#define ED    16
#define LYR   4
#define NB    32
#define EMAX  1024

// ---------------- scratch (device globals; allocation-free) ----------------
__device__ __half2 g_h16[(size_t)N_R * (H / 2)];
__device__ float   g_agg[(size_t)N_R * H];
__device__ float   g_hs[N_R];
__device__ float   g_hd[N_R];
__device__ __half2 g_ecsr[(size_t)N_E * (H / 2)];
__device__ float   g_ea[(size_t)N_E * 4];      // interleaved [p][l]
__device__ int     g_deg[N_R];
__device__ int     g_off[N_R + 1];
__device__ int     g_cur[N_R];
__device__ int     g_srcs[N_E];
__device__ int     g_perm[N_E];
__device__ int     g_gcnt[G_N];
__device__ int     g_goff[G_N + 1];
__device__ int     g_bsums[256];

__device__ __forceinline__ unsigned pack_half2(float a, float b) {
    __half2 h = __floats2half2_rn(a, b);
    return *reinterpret_cast<unsigned*>(&h);
}

// ---------------- fused setup kernels ----------------
__global__ void zero_fused(int* deg, int* cur, int* gcnt, int nN, int nG) {
    int i = blockIdx.x * blockDim.x + threadIdx.x;
    if (i < nN) { deg[i] = 0; cur[i] = 0; }
    if (i < nG) gcnt[i] = 0;
}
__global__ void hist_fused(const int* __restrict__ dst, const int* __restrict__ gid,
                           int* __restrict__ deg, int* __restrict__ gcnt,
                           int nE, int nN) {
    int i = blockIdx.x * blockDim.x + threadIdx.x;
    if (i < nE) atomicAdd(&deg[dst[i]], 1);
    if (i < nN) atomicAdd(&gcnt[gid[i]], 1);
}

// ---- multi-block exclusive scan ----
__global__ void scan_block(const int* __restrict__ cnt, int* __restrict__ off,
                           int* __restrict__ sums, int n) {
    __shared__ int wsum[32];
    int tid = threadIdx.x;
    int i = blockIdx.x * 1024 + tid;
    int v = (i < n) ? cnt[i] : 0;
    int x = v;
    #pragma unroll
    for (int d = 1; d < 32; d <<= 1) {
        int y = __shfl_up_sync(0xffffffffu, x, d);
        if ((tid & 31) >= d) x += y;
    }
    if ((tid & 31) == 31) wsum[tid >> 5] = x;
    __syncthreads();
    if (tid < 32) {
        int w = wsum[tid];
        #pragma unroll
        for (int d = 1; d < 32; d <<= 1) {
            int y = __shfl_up_sync(0xffffffffu, w, d);
            if (tid >= d) w += y;
        }
        wsum[tid] = w;
    }
    __syncthreads();
    int incl = x + ((tid >= 32) ? wsum[(tid >> 5) - 1] : 0);
    if (i < n) off[i + 1] = incl;
    if (tid == 1023) sums[blockIdx.x] = incl;
}
__global__ void scan_sums_par(int* sums, int nb) {
    __shared__ int ws[4];
    int tid = threadIdx.x;
    int lane = tid & 31;
    int v = (tid < nb) ? sums[tid] : 0;
    int x = v;
    #pragma unroll
    for (int d = 1; d < 32; d <<= 1) {
        int y = __shfl_up_sync(0xffffffffu, x, d);
        if (lane >= d) x += y;
    }
    if (lane == 31) ws[tid >> 5] = x;
    __syncthreads();
    if (tid == 0) {
        int a = 0;
        #pragma unroll
        for (int j = 0; j < 4; j++) { int t = ws[j]; ws[j] = a; a += t; }
    }
    __syncthreads();
    x += ws[tid >> 5];
    if (tid < nb) sums[tid] = x - v;
}
__global__ void add_base(int* __restrict__ off, const int* __restrict__ sums, int n) {
    int i = blockIdx.x * 1024 + threadIdx.x;
    if (i == 0) off[0] = 0;
    if (i < n) off[i + 1] += sums[blockIdx.x];
}

__global__ void scatter_kernel(const int* __restrict__ src, const int* __restrict__ dst,
                               const int* __restrict__ off, int* __restrict__ cur,
                               int* __restrict__ perm, int* __restrict__ srcs, int n) {
    int e = blockIdx.x * blockDim.x + threadIdx.x;
    if (e < n) {
        int d = dst[e];
        int p = off[d] + atomicAdd(&cur[d], 1);
        perm[p] = e;
        srcs[p] = src[e];
    }
}

// ---------------- tensor-core node GEMM — fp16-resident h -------------------
// out16 = fp16(maybe_lrelu(resid16 + in @ W)); fused hs/hd dots.
__global__ void __launch_bounds__(256)
gemm64_kernel(const float* __restrict__ in, const float* __restrict__ W,
              const __half2* __restrict__ resid16, __half2* __restrict__ out16,
              const float* __restrict__ as_, const float* __restrict__ ad_,
              float* __restrict__ hs, float* __restrict__ hd,
              int n, int do_lrelu) {
    __shared__ float  sW[64 * 64];
    __shared__ __half sA[64][72];
    __shared__ float  sRed[64][4];
    int tid = threadIdx.x;
    int lane = tid & 31;
    int w = tid >> 5;
    int wr = (w & 3) * 16;
    int cg = w >> 2;

    for (int i = tid; i < 4096; i += 256) sW[i] = W[i];
    __syncthreads();
    unsigned bfr[4][4][2];
    {
        int col = cg * 32 + (lane >> 2);
        int k0 = (lane & 3) * 2;
        #pragma unroll
        for (int f = 0; f < 4; f++) {
            int c = col + f * 8;
            #pragma unroll
            for (int s = 0; s < 4; s++) {
                int kk = s * 16 + k0;
                bfr[f][s][0] = pack_half2(sW[kk * 64 + c],       sW[(kk + 1) * 64 + c]);
                bfr[f][s][1] = pack_half2(sW[(kk + 8) * 64 + c], sW[(kk + 9) * 64 + c]);
            }
        }
    }

    float as0[8], ad0[8];
    if (as_) {
        #pragma unroll
        for (int f = 0; f < 4; f++) {
            int c = cg * 32 + f * 8 + 2 * (lane & 3);
            as0[2 * f]     = as_[c];     as0[2 * f + 1] = as_[c + 1];
            ad0[2 * f]     = ad_[c];     ad0[2 * f + 1] = ad_[c + 1];
        }
    }

    int ntiles = (n + 63) / 64;
    for (int t = blockIdx.x; t < ntiles; t += gridDim.x) {
        int base = t * 64;
        __syncthreads();
        for (int i = tid; i < 2048; i += 256) {
            int row = i >> 5;
            int k0 = (i & 31) * 2;
            int node = base + row;
            float2 v = (node < n) ? *(const float2*)(in + (size_t)node * H + k0)
                                  : make_float2(0.f, 0.f);
            *(__half2*)&sA[row][k0] = __floats2half2_rn(v.x, v.y);
        }
        __syncthreads();

        float c[4][4];
        #pragma unroll
        for (int f = 0; f < 4; f++)
            #pragma unroll
            for (int j = 0; j < 4; j++) c[f][j] = 0.f;

        int r = lane >> 2, k0 = (lane & 3) * 2;
        #pragma unroll
        for (int s = 0; s < 4; s++) {
            unsigned a0 = *(unsigned*)&sA[wr + r][s * 16 + k0];
            unsigned a1 = *(unsigned*)&sA[wr + r + 8][s * 16 + k0];
            unsigned a2 = *(unsigned*)&sA[wr + r][s * 16 + 8 + k0];
            unsigned a3 = *(unsigned*)&sA[wr + r + 8][s * 16 + 8 + k0];
            #pragma unroll
            for (int f = 0; f < 4; f++) {
                asm volatile(
                    "mma.sync.aligned.m16n8k16.row.col.f32.f16.f16.f32 "
                    "{%0,%1,%2,%3}, {%4,%5,%6,%7}, {%8,%9}, {%0,%1,%2,%3};"
                    : "+f"(c[f][0]), "+f"(c[f][1]), "+f"(c[f][2]), "+f"(c[f][3])
                    : "r"(a0), "r"(a1), "r"(a2), "r"(a3),
                      "r"(bfr[f][s][0]), "r"(bfr[f][s][1]));
            }
        }

        int rowA = wr + (lane >> 2);
        int rowB = rowA + 8;
        int nodeA = base + rowA;
        int nodeB = base + rowB;
        float psA = 0.f, pdA = 0.f, psB = 0.f, pdB = 0.f;
        #pragma unroll
        for (int f = 0; f < 4; f++) {
            int col = cg * 32 + f * 8 + 2 * (lane & 3);
            float v0 = c[f][0], v1 = c[f][1];
            float u0 = c[f][2], u1 = c[f][3];
            if (resid16) {
                if (nodeA < n) {
                    float2 rr = __half22float2(resid16[(size_t)nodeA * 32 + (col >> 1)]);
                    v0 += rr.x; v1 += rr.y;
                }
                if (nodeB < n) {
                    float2 rr = __half22float2(resid16[(size_t)nodeB * 32 + (col >> 1)]);
                    u0 += rr.x; u1 += rr.y;
                }
            }
            if (do_lrelu) {
                v0 = v0 > 0.f ? v0 : 0.1f * v0;  v1 = v1 > 0.f ? v1 : 0.1f * v1;
                u0 = u0 > 0.f ? u0 : 0.1f * u0;  u1 = u1 > 0.f ? u1 : 0.1f * u1;
            }
            if (nodeA < n)
                out16[(size_t)nodeA * 32 + (col >> 1)] = __floats2half2_rn(v0, v1);
            if (nodeB < n)
                out16[(size_t)nodeB * 32 + (col >> 1)] = __floats2half2_rn(u0, u1);
            if (as_) {
                psA += v0 * as0[2 * f] + v1 * as0[2 * f + 1];
                pdA += v0 * ad0[2 * f] + v1 * ad0[2 * f + 1];
                psB += u0 * as0[2 * f] + u1 * as0[2 * f + 1];
                pdB += u0 * ad0[2 * f] + u1 * ad0[2 * f + 1];
            }
        }
        if (as_) {
            #pragma unroll
            for (int d = 1; d < 4; d <<= 1) {
                psA += __shfl_xor_sync(0xffffffffu, psA, d);
                pdA += __shfl_xor_sync(0xffffffffu, pdA, d);
                psB += __shfl_xor_sync(0xffffffffu, psB, d);
                pdB += __shfl_xor_sync(0xffffffffu, pdB, d);
            }
            if ((lane & 3) == 0) {
                sRed[rowA][cg * 2 + 0] = psA;  sRed[rowA][cg * 2 + 1] = pdA;
                sRed[rowB][cg * 2 + 0] = psB;  sRed[rowB][cg * 2 + 1] = pdB;
            }
            __syncthreads();
            if (tid < 64 && base + tid < n) {
                hs[base + tid] = sRed[tid][0] + sRed[tid][2];
                hd[base + tid] = sRed[tid][1] + sRed[tid][3];
            }
        }
    }
}

// ---------------- build edge embeddings + interleaved logit terms -----------
__global__ void __launch_bounds__(256)
build_e_kernel(const float* __restrict__ r_edge,
               const float* __restrict__ W_e,
               const float* __restrict__ a_e,
               const int* __restrict__ perm,
               __half2* __restrict__ ecsr, float* __restrict__ ea,
               int n_e) {
    __shared__ float sWe[ED * H];
    __shared__ float sw16[LYR * ED];
    for (int i = threadIdx.x; i < ED * H; i += 256) sWe[i] = W_e[i];
    __syncthreads();
    if (threadIdx.x < LYR * ED) {
        int l = threadIdx.x >> 4, k = threadIdx.x & 15;
        float s = 0.f;
        for (int j = 0; j < H; j++) s += sWe[k * H + j] * a_e[l * H + j];
        sw16[threadIdx.x] = s;
    }
    __syncthreads();
    int lane = threadIdx.x & 31;
    int warp = (blockIdx.x * blockDim.x + threadIdx.x) >> 5;
    int nwarps = (gridDim.x * blockDim.x) >> 5;
    const float2* sWe2 = (const float2*)sWe;
    for (int p = warp; p < n_e; p += nwarps) {
        int eid = __ldg(&perm[p]);
        const float4* rp = (const float4*)(r_edge + (size_t)eid * ED);
        float4 q0 = rp[0], q1 = rp[1], q2 = rp[2], q3 = rp[3];
        float r[16] = {q0.x, q0.y, q0.z, q0.w, q1.x, q1.y, q1.z, q1.w,
                       q2.x, q2.y, q2.z, q2.w, q3.x, q3.y, q3.z, q3.w};
        float e0 = 0.f, e1 = 0.f;
        #pragma unroll
        for (int k = 0; k < 16; k++) {
            float2 wp = sWe2[k * 32 + lane];
            e0 += r[k] * wp.x;
            e1 += r[k] * wp.y;
        }
        ecsr[(size_t)p * 32 + lane] = __floats2half2_rn(e0, e1);
        if (lane < LYR) {
            float s = 0.f;
            #pragma unroll
            for (int k = 0; k < 16; k++) s += r[k] * sw16[lane * ED + k];
            ea[(size_t)p * 4 + lane] = s;
        }
    }
}

// ---------------- block-cooperative attention layer (R10) --------------------
__global__ void __launch_bounds__(256)
layer_kernel(const int* __restrict__ off, const int* __restrict__ srcs,
             const float* __restrict__ ea, int l,
             const float* __restrict__ hs, const float* __restrict__ hd,
             const __half2* __restrict__ h16, const __half2* __restrict__ ecsr,
             float* __restrict__ agg, int n) {
    __shared__ int   s_off[NB + 1];
    __shared__ float s_hd[NB];
    __shared__ float s_sum[NB];
    __shared__ float s_w[EMAX];
    __shared__ int   s_src[EMAX];
    int tid = threadIdx.x, lane = tid & 31, w = tid >> 5;
    int node0 = blockIdx.x * NB;
    if (tid <= NB) {
        int nd = node0 + tid;
        s_off[tid] = off[nd <= n ? nd : n];
    }
    if (tid < NB) {
        s_sum[tid] = 0.f;
        int nd = node0 + tid;
        s_hd[tid] = (nd < n) ? hd[nd] : 0.f;
    }
    __syncthreads();
    int base = s_off[0], endall = s_off[NB];
    float acc[4][2] = {{0.f,0.f},{0.f,0.f},{0.f,0.f},{0.f,0.f}};

    for (int cs = base; cs < endall; cs += EMAX) {
        int cnt = min(EMAX, endall - cs);
        for (int i = tid; i < cnt; i += 256) {
            int p = cs + i;
            int sv = __ldg(&srcs[p]);
            int lo = 0, hi = NB;
            #pragma unroll
            for (int b = 0; b < 5; b++) {
                int mid = (lo + hi) >> 1;
                bool ge = (p >= s_off[mid]);
                lo = ge ? mid : lo;
                hi = ge ? hi : mid;
            }
            float lg = __ldg(&hs[sv]) + s_hd[lo] + __ldg(&ea[(size_t)p * 4 + l]);
            lg = lg > 0.f ? lg : 0.1f * lg;
            float ew = __expf(fminf(lg, 85.f));
            s_w[i] = ew;
            s_src[i] = sv;
            atomicAdd(&s_sum[lo], ew);
        }
        __syncthreads();
        #pragma unroll
        for (int j = 0; j < 4; j++) {
            int ndl = w * 4 + j;
            int lo = max(s_off[ndl], cs) - cs;
            int hi = min(s_off[ndl + 1], cs + cnt) - cs;
            #pragma unroll 4
            for (int i = lo; i < hi; i++) {
                float wv = s_w[i];
                int sv = s_src[i];
                float2 hp = __half22float2(h16[(size_t)sv * 32 + lane]);
                float2 ep = __half22float2(ecsr[(size_t)(cs + i) * 32 + lane]);
                acc[j][0] += wv * (hp.x + ep.x);
                acc[j][1] += wv * (hp.y + ep.y);
            }
        }
        __syncthreads();
    }
    #pragma unroll
    for (int j = 0; j < 4; j++) {
        int ndl = w * 4 + j;
        int nd = node0 + ndl;
        if (nd < n) {
            float s = s_sum[ndl];
            float inv = (s > 0.f) ? (1.0f / s) : 0.f;
            *(float2*)(agg + (size_t)nd * H + 2 * lane) =
                make_float2(acc[j][0] * inv, acc[j][1] * inv);
        }
    }
}

// ---------------- fused pool + interaction + MLP readout (h16 input) --------
__global__ void __launch_bounds__(256)
poolmlp_kernel(const int* __restrict__ goff, const float* __restrict__ d_edge,
               const float* __restrict__ w_d, const float* __restrict__ b_d,
               const float* __restrict__ i_node, const float* __restrict__ W_i,
               const __half2* __restrict__ h16,
               const float* __restrict__ W_mlp, const float* __restrict__ b_mlp,
               const float* __restrict__ W_out, const float* __restrict__ b_out,
               float* __restrict__ out, int g_total) {
    __shared__ float sW[3 * 4096];
    __shared__ float sb[3 * 64];
    __shared__ float sWo[64];
    __shared__ float sx[8][64];
    int tid = threadIdx.x, lane = tid & 31, wl = tid >> 5;
    for (int i = tid; i < 3 * 4096; i += 256) sW[i] = W_mlp[i];
    if (tid < 192) sb[tid] = b_mlp[tid];
    if (tid < 64) sWo[tid] = W_out[tid];
    __syncthreads();
    float wd = w_d[0], bd = b_d[0], bo = b_out[0];
    int g = blockIdx.x * 8 + wl;
    if (g >= g_total) return;

    int beg = goff[g], end = goff[g + 1];
    float s00 = 0.f, s01 = 0.f, s10 = 0.f, s11 = 0.f, sg = 0.f;
    for (int nn = beg; nn < end; nn++) {
        float gate = 1.0f / (1.0f + __expf(-(d_edge[nn] * wd + bd)));
        float2 hp = __half22float2(h16[(size_t)nn * 32 + lane]);
        s00 += hp.x; s01 += hp.y;
        s10 += gate * hp.x; s11 += gate * hp.y;
        sg += gate;
    }
    float iv = i_node[g];
    float hi0 = iv * W_i[2 * lane] + s10;
    float hi1 = iv * W_i[2 * lane + 1] + s11;
    sx[wl][2 * lane]     = s00 + sg * hi0;
    sx[wl][2 * lane + 1] = s01 + sg * hi1;
    __syncwarp();

    for (int l = 0; l < 3; l++) {
        float a0 = sb[l * 64 + 2 * lane];
        float a1 = sb[l * 64 + 2 * lane + 1];
        const float* Wl = sW + l * 4096;
        #pragma unroll 8
        for (int k = 0; k < 64; k++) {
            float xv = sx[wl][k];
            a0 += xv * Wl[k * 64 + 2 * lane];
            a1 += xv * Wl[k * 64 + 2 * lane + 1];
        }
        a0 = fmaxf(a0, 0.f);
        a1 = fmaxf(a1, 0.f);
        __syncwarp();
        sx[wl][2 * lane]     = a0;
        sx[wl][2 * lane + 1] = a1;
        __syncwarp();
    }
    float part = sx[wl][2 * lane] * sWo[2 * lane] + sx[wl][2 * lane + 1] * sWo[2 * lane + 1];
    #pragma unroll
    for (int d = 16; d; d >>= 1) part += __shfl_xor_sync(0xffffffffu, part, d);
    if (lane == 0) out[g] = part + bo;
}

// ---------------- launcher ----------------
extern "C" void kernel_launch(void* const* d_in, const int* in_sizes, int n_in,
                              void* d_out, int out_size) {
    const float* r_node  = (const float*)d_in[0];
    const float* i_node  = (const float*)d_in[1];
    const float* r_edge  = (const float*)d_in[2];
    const float* d_edge  = (const float*)d_in[3];
    const int*   r2r_src = (const int*)d_in[4];
    const int*   r2r_dst = (const int*)d_in[5];
    const int*   graph_id= (const int*)d_in[6];
    const float* W_r     = (const float*)d_in[7];
    const float* W_i     = (const float*)d_in[8];
    const float* W_e     = (const float*)d_in[9];
    const float* Wm      = (const float*)d_in[10];
    const float* a_s     = (const float*)d_in[11];
    const float* a_d     = (const float*)d_in[12];
    const float* a_e     = (const float*)d_in[13];
    const float* w_d     = (const float*)d_in[14];
    const float* b_d     = (const float*)d_in[15];
    const float* W_mlp   = (const float*)d_in[16];
    const float* b_mlp   = (const float*)d_in[17];
    const float* W_out   = (const float*)d_in[18];
    const float* b_out   = (const float*)d_in[19];
    float* out = (float*)d_out;

    const int nN = in_sizes[3];
    const int nE = in_sizes[4];
    const int nG = in_sizes[1];

    float *p_agg, *p_hs, *p_hd, *p_ea;
    __half2 *p_ecsr, *p_h16;
    int *p_deg, *p_off, *p_cur, *p_srcs, *p_perm, *p_gcnt, *p_goff, *p_bsums;
    cudaGetSymbolAddress((void**)&p_h16, g_h16);
    cudaGetSymbolAddress((void**)&p_agg, g_agg);
    cudaGetSymbolAddress((void**)&p_hs, g_hs);
    cudaGetSymbolAddress((void**)&p_hd, g_hd);
    cudaGetSymbolAddress((void**)&p_ecsr, g_ecsr);
    cudaGetSymbolAddress((void**)&p_ea, g_ea);
    cudaGetSymbolAddress((void**)&p_deg, g_deg);
    cudaGetSymbolAddress((void**)&p_off, g_off);
    cudaGetSymbolAddress((void**)&p_cur, g_cur);
    cudaGetSymbolAddress((void**)&p_srcs, g_srcs);
    cudaGetSymbolAddress((void**)&p_perm, g_perm);
    cudaGetSymbolAddress((void**)&p_gcnt, g_gcnt);
    cudaGetSymbolAddress((void**)&p_goff, g_goff);
    cudaGetSymbolAddress((void**)&p_bsums, g_bsums);

    int nbN = (nN + 1023) / 1024;
    int nbG = (nG + 1023) / 1024;
    int layer_blocks = (nN + NB - 1) / NB;

    // 0: zero, 1: hist, 2: scanN, 3: gemm64 (ncu window)
    zero_fused<<<(nN + 255) / 256, 256>>>(p_deg, p_cur, p_gcnt, nN, nG);
    hist_fused<<<(nE + 255) / 256, 256>>>(r2r_dst, graph_id, p_deg, p_gcnt, nE, nN);
    scan_block<<<nbN, 1024>>>(p_deg, p_off, p_bsums, nN);
    gemm64_kernel<<<592, 256>>>(r_node, W_r, nullptr, p_h16,
                                a_s, a_d, p_hs, p_hd, nN, 0);
    scan_sums_par<<<1, 128>>>(p_bsums, nbN);
    add_base<<<nbN, 1024>>>(p_off, p_bsums, nN);
    scan_block<<<nbG, 1024>>>(p_gcnt, p_goff, p_bsums, nG);
    scan_sums_par<<<1, 128>>>(p_bsums, nbG);
    add_base<<<nbG, 1024>>>(p_goff, p_bsums, nG);
    scatter_kernel<<<(nE + 255) / 256, 256>>>(r2r_src, r2r_dst, p_off, p_cur,
                                              p_perm, p_srcs, nE);
    build_e_kernel<<<2048, 256>>>(r_edge, W_e, a_e, p_perm, p_ecsr, p_ea, nE);

    // DIAGNOSTIC: duplicate layer-0 (valid inputs; g_agg overwritten by real
    // layer-0 below before any consumer reads it -> output unchanged).
    // dur delta vs R10 isolates the true cost of one layer pass.
    layer_kernel<<<layer_blocks, 256>>>(p_off, p_srcs, p_ea, 0,
                                        p_hs, p_hd, p_h16, p_ecsr, p_agg, nN);

    // --- 4 attention conv layers ---
    for (int l = 0; l < LYR; l++) {
        layer_kernel<<<layer_blocks, 256>>>(p_off, p_srcs, p_ea, l,
                                            p_hs, p_hd, p_h16, p_ecsr, p_agg, nN);
        const float* as_next = (l < LYR - 1) ? (a_s + (l + 1) * H) : nullptr;
        const float* ad_next = (l < LYR - 1) ? (a_d + (l + 1) * H) : nullptr;
        gemm64_kernel<<<592, 256>>>(p_agg, Wm + (size_t)l * H * H, p_h16, p_h16,
                                    as_next, ad_next, p_hs, p_hd, nN, 1);
    }

    // --- fused pool + interaction + MLP ---
    poolmlp_kernel<<<(nG + 7) / 8, 256>>>(p_goff, d_edge, w_d, b_d, i_node, W_i,
                                          p_h16, W_mlp, b_mlp, W_out, b_out, out, nG);
}

// round 13
// speedup vs baseline: 2.1282x; 2.1282x over previous
#include <cuda_runtime.h>
#include <cuda_fp16.h>
#include <cstdint>

#define N_R   100000
#define N_E   1200000
#define G_N   4096
#define H     64
#define ED    16
#define LYR   4
#define NB    32
#define EMAX  512

// ---------------- scratch (device globals; allocation-free) ----------------
__device__ float   g_h[(size_t)N_R * H];
__device__ __half2 g_h16[(size_t)N_R * (H / 2)];
__device__ float   g_agg[(size_t)N_R * H];
__device__ float   g_hs[N_R];
__device__ float   g_hd[N_R];
__device__ uint4   g_recsr[(size_t)N_E * 2];    // r_edge fp16 CSR order: 2 x uint4 = 16 halfs
__device__ int     g_deg[N_R];
__device__ int     g_off[N_R + 1];
__device__ int     g_cur[N_R];
__device__ int     g_srcs[N_E];
__device__ int     g_perm[N_E];
__device__ int     g_gcnt[G_N];
__device__ int     g_goff[G_N + 1];
__device__ int     g_bsums[256];

__device__ __forceinline__ unsigned pack_half2(float a, float b) {
    __half2 h = __floats2half2_rn(a, b);
    return *reinterpret_cast<unsigned*>(&h);
}

// ---------------- fused setup kernels ----------------
__global__ void zero_fused(int* deg, int* cur, int* gcnt, int nN, int nG) {
    int i = blockIdx.x * blockDim.x + threadIdx.x;
    if (i < nN) { deg[i] = 0; cur[i] = 0; }
    if (i < nG) gcnt[i] = 0;
}
__global__ void hist_fused(const int* __restrict__ dst, const int* __restrict__ gid,
                           int* __restrict__ deg, int* __restrict__ gcnt,
                           int nE, int nN) {
    int i = blockIdx.x * blockDim.x + threadIdx.x;
    if (i < nE) atomicAdd(&deg[dst[i]], 1);
    if (i < nN) atomicAdd(&gcnt[gid[i]], 1);
}

// ---- multi-block exclusive scan ----
__global__ void scan_block(const int* __restrict__ cnt, int* __restrict__ off,
                           int* __restrict__ sums, int n) {
    __shared__ int wsum[32];
    int tid = threadIdx.x;
    int i = blockIdx.x * 1024 + tid;
    int v = (i < n) ? cnt[i] : 0;
    int x = v;
    #pragma unroll
    for (int d = 1; d < 32; d <<= 1) {
        int y = __shfl_up_sync(0xffffffffu, x, d);
        if ((tid & 31) >= d) x += y;
    }
    if ((tid & 31) == 31) wsum[tid >> 5] = x;
    __syncthreads();
    if (tid < 32) {
        int w = wsum[tid];
        #pragma unroll
        for (int d = 1; d < 32; d <<= 1) {
            int y = __shfl_up_sync(0xffffffffu, w, d);
            if (tid >= d) w += y;
        }
        wsum[tid] = w;
    }
    __syncthreads();
    int incl = x + ((tid >= 32) ? wsum[(tid >> 5) - 1] : 0);
    if (i < n) off[i + 1] = incl;
    if (tid == 1023) sums[blockIdx.x] = incl;
}
__global__ void scan_sums_par(int* sums, int nb) {
    __shared__ int ws[4];
    int tid = threadIdx.x;
    int lane = tid & 31;
    int v = (tid < nb) ? sums[tid] : 0;
    int x = v;
    #pragma unroll
    for (int d = 1; d < 32; d <<= 1) {
        int y = __shfl_up_sync(0xffffffffu, x, d);
        if (lane >= d) x += y;
    }
    if (lane == 31) ws[tid >> 5] = x;
    __syncthreads();
    if (tid == 0) {
        int a = 0;
        #pragma unroll
        for (int j = 0; j < 4; j++) { int t = ws[j]; ws[j] = a; a += t; }
    }
    __syncthreads();
    x += ws[tid >> 5];
    if (tid < nb) sums[tid] = x - v;
}
__global__ void add_base(int* __restrict__ off, const int* __restrict__ sums, int n) {
    int i = blockIdx.x * 1024 + threadIdx.x;
    if (i == 0) off[0] = 0;
    if (i < n) off[i + 1] += sums[blockIdx.x];
}

__global__ void scatter_kernel(const int* __restrict__ src, const int* __restrict__ dst,
                               const int* __restrict__ off, int* __restrict__ cur,
                               int* __restrict__ perm, int* __restrict__ srcs, int n) {
    int e = blockIdx.x * blockDim.x + threadIdx.x;
    if (e < n) {
        int d = dst[e];
        int p = off[d] + atomicAdd(&cur[d], 1);
        perm[p] = e;
        srcs[p] = src[e];
    }
}

// ---------------- tensor-core node GEMM (R10-proven, fp32 h + fp16 mirror) --
__global__ void __launch_bounds__(256)
gemm64_kernel(const float* __restrict__ in, const float* __restrict__ W,
              const float* __restrict__ resid, float* __restrict__ out,
              __half2* __restrict__ out16,
              const float* __restrict__ as_, const float* __restrict__ ad_,
              float* __restrict__ hs, float* __restrict__ hd,
              int n, int do_lrelu) {
    __shared__ float  sW[64 * 64];
    __shared__ __half sA[64][72];
    __shared__ float  sRed[64][4];
    int tid = threadIdx.x;
    int lane = tid & 31;
    int w = tid >> 5;
    int wr = (w & 3) * 16;
    int cg = w >> 2;

    for (int i = tid; i < 4096; i += 256) sW[i] = W[i];
    __syncthreads();
    unsigned bfr[4][4][2];
    {
        int col = cg * 32 + (lane >> 2);
        int k0 = (lane & 3) * 2;
        #pragma unroll
        for (int f = 0; f < 4; f++) {
            int c = col + f * 8;
            #pragma unroll
            for (int s = 0; s < 4; s++) {
                int kk = s * 16 + k0;
                bfr[f][s][0] = pack_half2(sW[kk * 64 + c],       sW[(kk + 1) * 64 + c]);
                bfr[f][s][1] = pack_half2(sW[(kk + 8) * 64 + c], sW[(kk + 9) * 64 + c]);
            }
        }
    }

    float as0[8], ad0[8];
    if (as_) {
        #pragma unroll
        for (int f = 0; f < 4; f++) {
            int c = cg * 32 + f * 8 + 2 * (lane & 3);
            as0[2 * f]     = as_[c];     as0[2 * f + 1] = as_[c + 1];
            ad0[2 * f]     = ad_[c];     ad0[2 * f + 1] = ad_[c + 1];
        }
    }

    int ntiles = (n + 63) / 64;
    for (int t = blockIdx.x; t < ntiles; t += gridDim.x) {
        int base = t * 64;
        __syncthreads();
        for (int i = tid; i < 2048; i += 256) {
            int row = i >> 5;
            int k0 = (i & 31) * 2;
            int node = base + row;
            float2 v = (node < n) ? *(const float2*)(in + (size_t)node * H + k0)
                                  : make_float2(0.f, 0.f);
            *(__half2*)&sA[row][k0] = __floats2half2_rn(v.x, v.y);
        }
        __syncthreads();

        float c[4][4];
        #pragma unroll
        for (int f = 0; f < 4; f++)
            #pragma unroll
            for (int j = 0; j < 4; j++) c[f][j] = 0.f;

        int r = lane >> 2, k0 = (lane & 3) * 2;
        #pragma unroll
        for (int s = 0; s < 4; s++) {
            unsigned a0 = *(unsigned*)&sA[wr + r][s * 16 + k0];
            unsigned a1 = *(unsigned*)&sA[wr + r + 8][s * 16 + k0];
            unsigned a2 = *(unsigned*)&sA[wr + r][s * 16 + 8 + k0];
            unsigned a3 = *(unsigned*)&sA[wr + r + 8][s * 16 + 8 + k0];
            #pragma unroll
            for (int f = 0; f < 4; f++) {
                asm volatile(
                    "mma.sync.aligned.m16n8k16.row.col.f32.f16.f16.f32 "
                    "{%0,%1,%2,%3}, {%4,%5,%6,%7}, {%8,%9}, {%0,%1,%2,%3};"
                    : "+f"(c[f][0]), "+f"(c[f][1]), "+f"(c[f][2]), "+f"(c[f][3])
                    : "r"(a0), "r"(a1), "r"(a2), "r"(a3),
                      "r"(bfr[f][s][0]), "r"(bfr[f][s][1]));
            }
        }

        int rowA = wr + (lane >> 2);
        int rowB = rowA + 8;
        int nodeA = base + rowA;
        int nodeB = base + rowB;
        float psA = 0.f, pdA = 0.f, psB = 0.f, pdB = 0.f;
        #pragma unroll
        for (int f = 0; f < 4; f++) {
            int col = cg * 32 + f * 8 + 2 * (lane & 3);
            float v0 = c[f][0], v1 = c[f][1];
            float u0 = c[f][2], u1 = c[f][3];
            if (resid) {
                if (nodeA < n) {
                    float2 rr = *(const float2*)(resid + (size_t)nodeA * H + col);
                    v0 += rr.x; v1 += rr.y;
                }
                if (nodeB < n) {
                    float2 rr = *(const float2*)(resid + (size_t)nodeB * H + col);
                    u0 += rr.x; u1 += rr.y;
                }
            }
            if (do_lrelu) {
                v0 = v0 > 0.f ? v0 : 0.1f * v0;  v1 = v1 > 0.f ? v1 : 0.1f * v1;
                u0 = u0 > 0.f ? u0 : 0.1f * u0;  u1 = u1 > 0.f ? u1 : 0.1f * u1;
            }
            if (nodeA < n) {
                *(float2*)(out + (size_t)nodeA * H + col) = make_float2(v0, v1);
                out16[(size_t)nodeA * 32 + (col >> 1)] = __floats2half2_rn(v0, v1);
            }
            if (nodeB < n) {
                *(float2*)(out + (size_t)nodeB * H + col) = make_float2(u0, u1);
                out16[(size_t)nodeB * 32 + (col >> 1)] = __floats2half2_rn(u0, u1);
            }
            if (as_) {
                psA += v0 * as0[2 * f] + v1 * as0[2 * f + 1];
                pdA += v0 * ad0[2 * f] + v1 * ad0[2 * f + 1];
                psB += u0 * as0[2 * f] + u1 * as0[2 * f + 1];
                pdB += u0 * ad0[2 * f] + u1 * ad0[2 * f + 1];
            }
        }
        if (as_) {
            #pragma unroll
            for (int d = 1; d < 4; d <<= 1) {
                psA += __shfl_xor_sync(0xffffffffu, psA, d);
                pdA += __shfl_xor_sync(0xffffffffu, pdA, d);
                psB += __shfl_xor_sync(0xffffffffu, psB, d);
                pdB += __shfl_xor_sync(0xffffffffu, pdB, d);
            }
            if ((lane & 3) == 0) {
                sRed[rowA][cg * 2 + 0] = psA;  sRed[rowA][cg * 2 + 1] = pdA;
                sRed[rowB][cg * 2 + 0] = psB;  sRed[rowB][cg * 2 + 1] = pdB;
            }
            __syncthreads();
            if (tid < 64 && base + tid < n) {
                hs[base + tid] = sRed[tid][0] + sRed[tid][2];
                hd[base + tid] = sRed[tid][1] + sRed[tid][3];
            }
        }
    }
}

// ---------------- build recsr: gather r_edge rows into CSR order (fp16) -----
__global__ void __launch_bounds__(256)
build_recsr_kernel(const float* __restrict__ r_edge, const int* __restrict__ perm,
                   uint4* __restrict__ recsr, int n_e) {
    int p = blockIdx.x * blockDim.x + threadIdx.x;
    if (p >= n_e) return;
    int eid = __ldg(&perm[p]);
    const float4* rp = (const float4*)(r_edge + (size_t)eid * ED);
    float4 q0 = rp[0], q1 = rp[1], q2 = rp[2], q3 = rp[3];
    __half2 hv[8];
    hv[0] = __floats2half2_rn(q0.x, q0.y);
    hv[1] = __floats2half2_rn(q0.z, q0.w);
    hv[2] = __floats2half2_rn(q1.x, q1.y);
    hv[3] = __floats2half2_rn(q1.z, q1.w);
    hv[4] = __floats2half2_rn(q2.x, q2.y);
    hv[5] = __floats2half2_rn(q2.z, q2.w);
    hv[6] = __floats2half2_rn(q3.x, q3.y);
    hv[7] = __floats2half2_rn(q3.z, q3.w);
    recsr[(size_t)p * 2]     = *(uint4*)&hv[0];
    recsr[(size_t)p * 2 + 1] = *(uint4*)&hv[4];
}

// ---------------- block-cooperative attention layer, 16-dim edge aggregation -
__global__ void __launch_bounds__(256)
layer_kernel(const int* __restrict__ off, const int* __restrict__ srcs,
             const uint4* __restrict__ recsr,
             const float* __restrict__ W_e, const float* __restrict__ a_e, int l,
             const float* __restrict__ hs, const float* __restrict__ hd,
             const __half2* __restrict__ h16,
             float* __restrict__ agg, int n) {
    __shared__ float  sWe[ED * H];       // 4 KB
    __shared__ float  sw16[ED];
    __shared__ int    s_off[NB + 1];
    __shared__ float  s_hd[NB];
    __shared__ float  s_sum[NB];
    __shared__ float  s_w[EMAX];         // 2 KB
    __shared__ int    s_src[EMAX];       // 2 KB
    __shared__ uint4  s_re[EMAX * 2];    // 16 KB, 16B aligned
    int tid = threadIdx.x, lane = tid & 31, w = tid >> 5;
    int node0 = blockIdx.x * NB;
    for (int i = tid; i < ED * H; i += 256) sWe[i] = W_e[i];
    if (tid <= NB) {
        int nd = node0 + tid;
        s_off[tid] = off[nd <= n ? nd : n];
    }
    if (tid < NB) {
        s_sum[tid] = 0.f;
        int nd = node0 + tid;
        s_hd[tid] = (nd < n) ? hd[nd] : 0.f;
    }
    __syncthreads();
    if (tid < ED) {
        float s = 0.f;
        const float* ae = a_e + l * H;
        #pragma unroll 8
        for (int j = 0; j < H; j++) s += sWe[tid * H + j] * ae[j];
        sw16[tid] = s;
    }
    __syncthreads();

    int base = s_off[0], endall = s_off[NB];
    float acc[4][2] = {{0.f,0.f},{0.f,0.f},{0.f,0.f},{0.f,0.f}};
    float acc16[4] = {0.f, 0.f, 0.f, 0.f};

    for (int cs = base; cs < endall; cs += EMAX) {
        int cnt = min(EMAX, endall - cs);
        // phase 1: edge-parallel exp(logit), coalesced srcs/recsr
        for (int i = tid; i < cnt; i += 256) {
            int p = cs + i;
            int sv = __ldg(&srcs[p]);
            uint4 ra = __ldg(&recsr[(size_t)p * 2]);
            uint4 rb = __ldg(&recsr[(size_t)p * 2 + 1]);
            const __half2* ha = (const __half2*)&ra;
            const __half2* hb = (const __half2*)&rb;
            float ea = 0.f;
            #pragma unroll
            for (int j = 0; j < 4; j++) {
                float2 f = __half22float2(ha[j]);
                ea += f.x * sw16[2 * j] + f.y * sw16[2 * j + 1];
            }
            #pragma unroll
            for (int j = 0; j < 4; j++) {
                float2 f = __half22float2(hb[j]);
                ea += f.x * sw16[8 + 2 * j] + f.y * sw16[8 + 2 * j + 1];
            }
            int lo = 0, hi = NB;
            #pragma unroll
            for (int b = 0; b < 5; b++) {
                int mid = (lo + hi) >> 1;
                bool ge = (p >= s_off[mid]);
                lo = ge ? mid : lo;
                hi = ge ? hi : mid;
            }
            float lg = __ldg(&hs[sv]) + s_hd[lo] + ea;
            lg = lg > 0.f ? lg : 0.1f * lg;
            float ew = __expf(fminf(lg, 85.f));
            s_w[i] = ew;
            s_src[i] = sv;
            s_re[i * 2]     = ra;
            s_re[i * 2 + 1] = rb;
            atomicAdd(&s_sum[lo], ew);
        }
        __syncthreads();
        // phase 2: warp per 4 nodes, weighted gather + 16-dim edge accumulation
        const __half* s_reh = (const __half*)s_re;
        #pragma unroll
        for (int j = 0; j < 4; j++) {
            int ndl = w * 4 + j;
            int lo = max(s_off[ndl], cs) - cs;
            int hi = min(s_off[ndl + 1], cs + cnt) - cs;
            #pragma unroll 4
            for (int i = lo; i < hi; i++) {
                float wv = s_w[i];
                int sv = s_src[i];
                float2 hp = __half22float2(h16[(size_t)sv * 32 + lane]);
                acc[j][0] += wv * hp.x;
                acc[j][1] += wv * hp.y;
                if (lane < ED)
                    acc16[j] += wv * __half2float(s_reh[i * ED + lane]);
            }
        }
        __syncthreads();
    }
    // epilogue: add (acc16 @ W_e) and normalize
    #pragma unroll
    for (int j = 0; j < 4; j++) {
        int ndl = w * 4 + j;
        int nd = node0 + ndl;
        float a0 = acc[j][0], a1 = acc[j][1];
        #pragma unroll
        for (int k = 0; k < ED; k++) {
            float b = __shfl_sync(0xffffffffu, acc16[j], k);
            a0 += b * sWe[k * H + 2 * lane];
            a1 += b * sWe[k * H + 2 * lane + 1];
        }
        if (nd < n) {
            float s = s_sum[ndl];
            float inv = (s > 0.f) ? (1.0f / s) : 0.f;
            *(float2*)(agg + (size_t)nd * H + 2 * lane) =
                make_float2(a0 * inv, a1 * inv);
        }
    }
}

// ---------------- fused pool + interaction + MLP readout (warp per graph) ----
__global__ void __launch_bounds__(256)
poolmlp_kernel(const int* __restrict__ goff, const float* __restrict__ d_edge,
               const float* __restrict__ w_d, const float* __restrict__ b_d,
               const float* __restrict__ i_node, const float* __restrict__ W_i,
               const float* __restrict__ h,
               const float* __restrict__ W_mlp, const float* __restrict__ b_mlp,
               const float* __restrict__ W_out, const float* __restrict__ b_out,
               float* __restrict__ out, int g_total) {
    __shared__ float sW[3 * 4096];
    __shared__ float sb[3 * 64];
    __shared__ float sWo[64];
    __shared__ float sx[8][64];
    int tid = threadIdx.x, lane = tid & 31, wl = tid >> 5;
    for (int i = tid; i < 3 * 4096; i += 256) sW[i] = W_mlp[i];
    if (tid < 192) sb[tid] = b_mlp[tid];
    if (tid < 64) sWo[tid] = W_out[tid];
    __syncthreads();
    float wd = w_d[0], bd = b_d[0], bo = b_out[0];
    int g = blockIdx.x * 8 + wl;
    if (g >= g_total) return;

    int beg = goff[g], end = goff[g + 1];
    float s00 = 0.f, s01 = 0.f, s10 = 0.f, s11 = 0.f, sg = 0.f;
    for (int nn = beg; nn < end; nn++) {
        float gate = 1.0f / (1.0f + __expf(-(d_edge[nn] * wd + bd)));
        float2 hp = *(const float2*)(h + (size_t)nn * H + 2 * lane);
        s00 += hp.x; s01 += hp.y;
        s10 += gate * hp.x; s11 += gate * hp.y;
        sg += gate;
    }
    float iv = i_node[g];
    float hi0 = iv * W_i[2 * lane] + s10;
    float hi1 = iv * W_i[2 * lane + 1] + s11;
    sx[wl][2 * lane]     = s00 + sg * hi0;
    sx[wl][2 * lane + 1] = s01 + sg * hi1;
    __syncwarp();

    for (int l = 0; l < 3; l++) {
        float a0 = sb[l * 64 + 2 * lane];
        float a1 = sb[l * 64 + 2 * lane + 1];
        const float* Wl = sW + l * 4096;
        #pragma unroll 8
        for (int k = 0; k < 64; k++) {
            float xv = sx[wl][k];
            a0 += xv * Wl[k * 64 + 2 * lane];
            a1 += xv * Wl[k * 64 + 2 * lane + 1];
        }
        a0 = fmaxf(a0, 0.f);
        a1 = fmaxf(a1, 0.f);
        __syncwarp();
        sx[wl][2 * lane]     = a0;
        sx[wl][2 * lane + 1] = a1;
        __syncwarp();
    }
    float part = sx[wl][2 * lane] * sWo[2 * lane] + sx[wl][2 * lane + 1] * sWo[2 * lane + 1];
    #pragma unroll
    for (int d = 16; d; d >>= 1) part += __shfl_xor_sync(0xffffffffu, part, d);
    if (lane == 0) out[g] = part + bo;
}

// ---------------- launcher ----------------
extern "C" void kernel_launch(void* const* d_in, const int* in_sizes, int n_in,
                              void* d_out, int out_size) {
    const float* r_node  = (const float*)d_in[0];
    const float* i_node  = (const float*)d_in[1];
    const float* r_edge  = (const float*)d_in[2];
    const float* d_edge  = (const float*)d_in[3];
    const int*   r2r_src = (const int*)d_in[4];
    const int*   r2r_dst = (const int*)d_in[5];
    const int*   graph_id= (const int*)d_in[6];
    const float* W_r     = (const float*)d_in[7];
    const float* W_i     = (const float*)d_in[8];
    const float* W_e     = (const float*)d_in[9];
    const float* Wm      = (const float*)d_in[10];
    const float* a_s     = (const float*)d_in[11];
    const float* a_d     = (const float*)d_in[12];
    const float* a_e     = (const float*)d_in[13];
    const float* w_d     = (const float*)d_in[14];
    const float* b_d     = (const float*)d_in[15];
    const float* W_mlp   = (const float*)d_in[16];
    const float* b_mlp   = (const float*)d_in[17];
    const float* W_out   = (const float*)d_in[18];
    const float* b_out   = (const float*)d_in[19];
    float* out = (float*)d_out;

    const int nN = in_sizes[3];
    const int nE = in_sizes[4];
    const int nG = in_sizes[1];

    float *p_h, *p_agg, *p_hs, *p_hd;
    __half2* p_h16;
    uint4*   p_recsr;
    int *p_deg, *p_off, *p_cur, *p_srcs, *p_perm, *p_gcnt, *p_goff, *p_bsums;
    cudaGetSymbolAddress((void**)&p_h, g_h);
    cudaGetSymbolAddress((void**)&p_h16, g_h16);
    cudaGetSymbolAddress((void**)&p_agg, g_agg);
    cudaGetSymbolAddress((void**)&p_hs, g_hs);
    cudaGetSymbolAddress((void**)&p_hd, g_hd);
    cudaGetSymbolAddress((void**)&p_recsr, g_recsr);
    cudaGetSymbolAddress((void**)&p_deg, g_deg);
    cudaGetSymbolAddress((void**)&p_off, g_off);
    cudaGetSymbolAddress((void**)&p_cur, g_cur);
    cudaGetSymbolAddress((void**)&p_srcs, g_srcs);
    cudaGetSymbolAddress((void**)&p_perm, g_perm);
    cudaGetSymbolAddress((void**)&p_gcnt, g_gcnt);
    cudaGetSymbolAddress((void**)&p_goff, g_goff);
    cudaGetSymbolAddress((void**)&p_bsums, g_bsums);

    int nbN = (nN + 1023) / 1024;
    int nbG = (nG + 1023) / 1024;
    int layer_blocks = (nN + NB - 1) / NB;

    // 0: zero, 1: hist, 2: scanN, 3: gemm64 (ncu window)
    zero_fused<<<(nN + 255) / 256, 256>>>(p_deg, p_cur, p_gcnt, nN, nG);
    hist_fused<<<(nE + 255) / 256, 256>>>(r2r_dst, graph_id, p_deg, p_gcnt, nE, nN);
    scan_block<<<nbN, 1024>>>(p_deg, p_off, p_bsums, nN);
    gemm64_kernel<<<592, 256>>>(r_node, W_r, nullptr, p_h, p_h16,
                                a_s, a_d, p_hs, p_hd, nN, 0);
    scan_sums_par<<<1, 128>>>(p_bsums, nbN);
    add_base<<<nbN, 1024>>>(p_off, p_bsums, nN);
    scan_block<<<nbG, 1024>>>(p_gcnt, p_goff, p_bsums, nG);
    scan_sums_par<<<1, 128>>>(p_bsums, nbG);
    add_base<<<nbG, 1024>>>(p_goff, p_bsums, nG);
    scatter_kernel<<<(nE + 255) / 256, 256>>>(r2r_src, r2r_dst, p_off, p_cur,
                                              p_perm, p_srcs, nE);
    build_recsr_kernel<<<(nE + 255) / 256, 256>>>(r_edge, p_perm, p_recsr, nE);

    // --- 4 attention conv layers ---
    for (int l = 0; l < LYR; l++) {
        layer_kernel<<<layer_blocks, 256>>>(p_off, p_srcs, p_recsr, W_e, a_e, l,
                                            p_hs, p_hd, p_h16, p_agg, nN);
        const float* as_next = (l < LYR - 1) ? (a_s + (l + 1) * H) : nullptr;
        const float* ad_next = (l < LYR - 1) ? (a_d + (l + 1) * H) : nullptr;
        gemm64_kernel<<<592, 256>>>(p_agg, Wm + (size_t)l * H * H, p_h, p_h, p_h16,
                                    as_next, ad_next, p_hs, p_hd, nN, 1);
    }

    // --- fused pool + interaction + MLP ---
    poolmlp_kernel<<<(nG + 7) / 8, 256>>>(p_goff, d_edge, w_d, b_d, i_node, W_i,
                                          p_h, W_mlp, b_mlp, W_out, b_out, out, nG);
}

// round 14
// speedup vs baseline: 2.2026x; 1.0349x over previous
#include <cuda_runtime.h>
#include <cuda_fp16.h>
#include <cstdint>

#define N_R   100000
#define N_E   1200000
#define G_N   4096
#define H     64
#define ED    16
#define LYR   4
#define NB    32
#define EMAX  512

// ---------------- scratch (device globals; allocation-free) ----------------
__device__ float   g_h[(size_t)N_R * H];
__device__ __half2 g_h16[(size_t)N_R * (H / 2)];
__device__ __half2 g_agg16[(size_t)N_R * (H / 2)];
__device__ float   g_hs[N_R];
__device__ float   g_hd[N_R];
__device__ uint4   g_recsr[(size_t)N_E * 2];    // r_edge fp16 CSR order
__device__ int     g_deg[N_R];
__device__ int     g_off[N_R + 1];
__device__ int     g_cur[N_R];
__device__ int     g_srcs[N_E];
__device__ int     g_perm[N_E];
__device__ int     g_gcnt[G_N];
__device__ int     g_goff[G_N + 1];
__device__ int     g_bsums[256];

__device__ __forceinline__ unsigned pack_half2(float a, float b) {
    __half2 h = __floats2half2_rn(a, b);
    return *reinterpret_cast<unsigned*>(&h);
}

// ---------------- fused setup kernels ----------------
__global__ void zero_fused(int* deg, int* cur, int* gcnt, int nN, int nG) {
    int i = blockIdx.x * blockDim.x + threadIdx.x;
    if (i < nN) { deg[i] = 0; cur[i] = 0; }
    if (i < nG) gcnt[i] = 0;
}
__global__ void hist_fused(const int* __restrict__ dst, const int* __restrict__ gid,
                           int* __restrict__ deg, int* __restrict__ gcnt,
                           int nE, int nN) {
    int i = blockIdx.x * blockDim.x + threadIdx.x;
    if (i < nE) atomicAdd(&deg[dst[i]], 1);
    if (i < nN) atomicAdd(&gcnt[gid[i]], 1);
}

// ---- multi-block exclusive scan ----
__global__ void scan_block(const int* __restrict__ cnt, int* __restrict__ off,
                           int* __restrict__ sums, int n) {
    __shared__ int wsum[32];
    int tid = threadIdx.x;
    int i = blockIdx.x * 1024 + tid;
    int v = (i < n) ? cnt[i] : 0;
    int x = v;
    #pragma unroll
    for (int d = 1; d < 32; d <<= 1) {
        int y = __shfl_up_sync(0xffffffffu, x, d);
        if ((tid & 31) >= d) x += y;
    }
    if ((tid & 31) == 31) wsum[tid >> 5] = x;
    __syncthreads();
    if (tid < 32) {
        int w = wsum[tid];
        #pragma unroll
        for (int d = 1; d < 32; d <<= 1) {
            int y = __shfl_up_sync(0xffffffffu, w, d);
            if (tid >= d) w += y;
        }
        wsum[tid] = w;
    }
    __syncthreads();
    int incl = x + ((tid >= 32) ? wsum[(tid >> 5) - 1] : 0);
    if (i < n) off[i + 1] = incl;
    if (tid == 1023) sums[blockIdx.x] = incl;
}
__global__ void scan_sums_par(int* sums, int nb) {
    __shared__ int ws[4];
    int tid = threadIdx.x;
    int lane = tid & 31;
    int v = (tid < nb) ? sums[tid] : 0;
    int x = v;
    #pragma unroll
    for (int d = 1; d < 32; d <<= 1) {
        int y = __shfl_up_sync(0xffffffffu, x, d);
        if (lane >= d) x += y;
    }
    if (lane == 31) ws[tid >> 5] = x;
    __syncthreads();
    if (tid == 0) {
        int a = 0;
        #pragma unroll
        for (int j = 0; j < 4; j++) { int t = ws[j]; ws[j] = a; a += t; }
    }
    __syncthreads();
    x += ws[tid >> 5];
    if (tid < nb) sums[tid] = x - v;
}
__global__ void add_base(int* __restrict__ off, const int* __restrict__ sums, int n) {
    int i = blockIdx.x * 1024 + threadIdx.x;
    if (i == 0) off[0] = 0;
    if (i < n) off[i + 1] += sums[blockIdx.x];
}

__global__ void scatter_kernel(const int* __restrict__ src, const int* __restrict__ dst,
                               const int* __restrict__ off, int* __restrict__ cur,
                               int* __restrict__ perm, int* __restrict__ srcs, int n) {
    int e = blockIdx.x * blockDim.x + threadIdx.x;
    if (e < n) {
        int d = dst[e];
        int p = off[d] + atomicAdd(&cur[d], 1);
        perm[p] = e;
        srcs[p] = src[e];
    }
}

// ---------------- tensor-core node GEMM --------------------------------------
// Input either fp32 (in32) or fp16 (in16) — exactly one non-null.
__global__ void __launch_bounds__(256)
gemm64_kernel(const float* __restrict__ in32, const __half2* __restrict__ in16,
              const float* __restrict__ W,
              const float* __restrict__ resid, float* __restrict__ out,
              __half2* __restrict__ out16,
              const float* __restrict__ as_, const float* __restrict__ ad_,
              float* __restrict__ hs, float* __restrict__ hd,
              int n, int do_lrelu) {
    __shared__ float  sW[64 * 64];
    __shared__ __half sA[64][72];
    __shared__ float  sRed[64][4];
    int tid = threadIdx.x;
    int lane = tid & 31;
    int w = tid >> 5;
    int wr = (w & 3) * 16;
    int cg = w >> 2;

    for (int i = tid; i < 4096; i += 256) sW[i] = W[i];
    __syncthreads();
    unsigned bfr[4][4][2];
    {
        int col = cg * 32 + (lane >> 2);
        int k0 = (lane & 3) * 2;
        #pragma unroll
        for (int f = 0; f < 4; f++) {
            int c = col + f * 8;
            #pragma unroll
            for (int s = 0; s < 4; s++) {
                int kk = s * 16 + k0;
                bfr[f][s][0] = pack_half2(sW[kk * 64 + c],       sW[(kk + 1) * 64 + c]);
                bfr[f][s][1] = pack_half2(sW[(kk + 8) * 64 + c], sW[(kk + 9) * 64 + c]);
            }
        }
    }

    float as0[8], ad0[8];
    if (as_) {
        #pragma unroll
        for (int f = 0; f < 4; f++) {
            int c = cg * 32 + f * 8 + 2 * (lane & 3);
            as0[2 * f]     = as_[c];     as0[2 * f + 1] = as_[c + 1];
            ad0[2 * f]     = ad_[c];     ad0[2 * f + 1] = ad_[c + 1];
        }
    }

    int ntiles = (n + 63) / 64;
    for (int t = blockIdx.x; t < ntiles; t += gridDim.x) {
        int base = t * 64;
        __syncthreads();
        if (in16) {
            for (int i = tid; i < 2048; i += 256) {       // 64 rows x 32 half2
                int row = i >> 5;
                int k2 = i & 31;
                int node = base + row;
                __half2 v = (node < n) ? in16[(size_t)node * 32 + k2]
                                       : __floats2half2_rn(0.f, 0.f);
                *(__half2*)&sA[row][k2 * 2] = v;
            }
        } else {
            for (int i = tid; i < 2048; i += 256) {
                int row = i >> 5;
                int k0 = (i & 31) * 2;
                int node = base + row;
                float2 v = (node < n) ? *(const float2*)(in32 + (size_t)node * H + k0)
                                      : make_float2(0.f, 0.f);
                *(__half2*)&sA[row][k0] = __floats2half2_rn(v.x, v.y);
            }
        }
        __syncthreads();

        float c[4][4];
        #pragma unroll
        for (int f = 0; f < 4; f++)
            #pragma unroll
            for (int j = 0; j < 4; j++) c[f][j] = 0.f;

        int r = lane >> 2, k0 = (lane & 3) * 2;
        #pragma unroll
        for (int s = 0; s < 4; s++) {
            unsigned a0 = *(unsigned*)&sA[wr + r][s * 16 + k0];
            unsigned a1 = *(unsigned*)&sA[wr + r + 8][s * 16 + k0];
            unsigned a2 = *(unsigned*)&sA[wr + r][s * 16 + 8 + k0];
            unsigned a3 = *(unsigned*)&sA[wr + r + 8][s * 16 + 8 + k0];
            #pragma unroll
            for (int f = 0; f < 4; f++) {
                asm volatile(
                    "mma.sync.aligned.m16n8k16.row.col.f32.f16.f16.f32 "
                    "{%0,%1,%2,%3}, {%4,%5,%6,%7}, {%8,%9}, {%0,%1,%2,%3};"
                    : "+f"(c[f][0]), "+f"(c[f][1]), "+f"(c[f][2]), "+f"(c[f][3])
                    : "r"(a0), "r"(a1), "r"(a2), "r"(a3),
                      "r"(bfr[f][s][0]), "r"(bfr[f][s][1]));
            }
        }

        int rowA = wr + (lane >> 2);
        int rowB = rowA + 8;
        int nodeA = base + rowA;
        int nodeB = base + rowB;
        float psA = 0.f, pdA = 0.f, psB = 0.f, pdB = 0.f;
        #pragma unroll
        for (int f = 0; f < 4; f++) {
            int col = cg * 32 + f * 8 + 2 * (lane & 3);
            float v0 = c[f][0], v1 = c[f][1];
            float u0 = c[f][2], u1 = c[f][3];
            if (resid) {
                if (nodeA < n) {
                    float2 rr = *(const float2*)(resid + (size_t)nodeA * H + col);
                    v0 += rr.x; v1 += rr.y;
                }
                if (nodeB < n) {
                    float2 rr = *(const float2*)(resid + (size_t)nodeB * H + col);
                    u0 += rr.x; u1 += rr.y;
                }
            }
            if (do_lrelu) {
                v0 = v0 > 0.f ? v0 : 0.1f * v0;  v1 = v1 > 0.f ? v1 : 0.1f * v1;
                u0 = u0 > 0.f ? u0 : 0.1f * u0;  u1 = u1 > 0.f ? u1 : 0.1f * u1;
            }
            if (nodeA < n) {
                *(float2*)(out + (size_t)nodeA * H + col) = make_float2(v0, v1);
                out16[(size_t)nodeA * 32 + (col >> 1)] = __floats2half2_rn(v0, v1);
            }
            if (nodeB < n) {
                *(float2*)(out + (size_t)nodeB * H + col) = make_float2(u0, u1);
                out16[(size_t)nodeB * 32 + (col >> 1)] = __floats2half2_rn(u0, u1);
            }
            if (as_) {
                psA += v0 * as0[2 * f] + v1 * as0[2 * f + 1];
                pdA += v0 * ad0[2 * f] + v1 * ad0[2 * f + 1];
                psB += u0 * as0[2 * f] + u1 * as0[2 * f + 1];
                pdB += u0 * ad0[2 * f] + u1 * ad0[2 * f + 1];
            }
        }
        if (as_) {
            #pragma unroll
            for (int d = 1; d < 4; d <<= 1) {
                psA += __shfl_xor_sync(0xffffffffu, psA, d);
                pdA += __shfl_xor_sync(0xffffffffu, pdA, d);
                psB += __shfl_xor_sync(0xffffffffu, psB, d);
                pdB += __shfl_xor_sync(0xffffffffu, pdB, d);
            }
            if ((lane & 3) == 0) {
                sRed[rowA][cg * 2 + 0] = psA;  sRed[rowA][cg * 2 + 1] = pdA;
                sRed[rowB][cg * 2 + 0] = psB;  sRed[rowB][cg * 2 + 1] = pdB;
            }
            __syncthreads();
            if (tid < 64 && base + tid < n) {
                hs[base + tid] = sRed[tid][0] + sRed[tid][2];
                hd[base + tid] = sRed[tid][1] + sRed[tid][3];
            }
        }
    }
}

// ---------------- build recsr: gather r_edge rows into CSR order (fp16) -----
__global__ void __launch_bounds__(256)
build_recsr_kernel(const float* __restrict__ r_edge, const int* __restrict__ perm,
                   uint4* __restrict__ recsr, int n_e) {
    int p = blockIdx.x * blockDim.x + threadIdx.x;
    if (p >= n_e) return;
    int eid = __ldg(&perm[p]);
    const float4* rp = (const float4*)(r_edge + (size_t)eid * ED);
    float4 q0 = rp[0], q1 = rp[1], q2 = rp[2], q3 = rp[3];
    __half2 hv[8];
    hv[0] = __floats2half2_rn(q0.x, q0.y);
    hv[1] = __floats2half2_rn(q0.z, q0.w);
    hv[2] = __floats2half2_rn(q1.x, q1.y);
    hv[3] = __floats2half2_rn(q1.z, q1.w);
    hv[4] = __floats2half2_rn(q2.x, q2.y);
    hv[5] = __floats2half2_rn(q2.z, q2.w);
    hv[6] = __floats2half2_rn(q3.x, q3.y);
    hv[7] = __floats2half2_rn(q3.z, q3.w);
    recsr[(size_t)p * 2]     = *(uint4*)&hv[0];
    recsr[(size_t)p * 2 + 1] = *(uint4*)&hv[4];
}

// ---------------- block-cooperative attention layer (R13-proven) -------------
// agg16 = fp16((Σ ew·h[src] + (Σ ew·r_edge) @ W_e) / Σ ew)
__global__ void __launch_bounds__(256)
layer_kernel(const int* __restrict__ off, const int* __restrict__ srcs,
             const uint4* __restrict__ recsr,
             const float* __restrict__ W_e, const float* __restrict__ a_e, int l,
             const float* __restrict__ hs, const float* __restrict__ hd,
             const __half2* __restrict__ h16,
             __half2* __restrict__ agg16, int n) {
    __shared__ float  sWe[ED * H];
    __shared__ float  sw16[ED];
    __shared__ int    s_off[NB + 1];
    __shared__ float  s_hd[NB];
    __shared__ float  s_sum[NB];
    __shared__ float  s_w[EMAX];
    __shared__ int    s_src[EMAX];
    __shared__ uint4  s_re[EMAX * 2];
    int tid = threadIdx.x, lane = tid & 31, w = tid >> 5;
    int node0 = blockIdx.x * NB;
    for (int i = tid; i < ED * H; i += 256) sWe[i] = W_e[i];
    if (tid <= NB) {
        int nd = node0 + tid;
        s_off[tid] = off[nd <= n ? nd : n];
    }
    if (tid < NB) {
        s_sum[tid] = 0.f;
        int nd = node0 + tid;
        s_hd[tid] = (nd < n) ? hd[nd] : 0.f;
    }
    __syncthreads();
    if (tid < ED) {
        float s = 0.f;
        const float* ae = a_e + l * H;
        #pragma unroll 8
        for (int j = 0; j < H; j++) s += sWe[tid * H + j] * ae[j];
        sw16[tid] = s;
    }
    __syncthreads();

    int base = s_off[0], endall = s_off[NB];
    float acc[4][2] = {{0.f,0.f},{0.f,0.f},{0.f,0.f},{0.f,0.f}};
    float acc16[4] = {0.f, 0.f, 0.f, 0.f};

    for (int cs = base; cs < endall; cs += EMAX) {
        int cnt = min(EMAX, endall - cs);
        for (int i = tid; i < cnt; i += 256) {
            int p = cs + i;
            int sv = __ldg(&srcs[p]);
            uint4 ra = __ldg(&recsr[(size_t)p * 2]);
            uint4 rb = __ldg(&recsr[(size_t)p * 2 + 1]);
            const __half2* ha = (const __half2*)&ra;
            const __half2* hb = (const __half2*)&rb;
            float ea = 0.f;
            #pragma unroll
            for (int j = 0; j < 4; j++) {
                float2 f = __half22float2(ha[j]);
                ea += f.x * sw16[2 * j] + f.y * sw16[2 * j + 1];
            }
            #pragma unroll
            for (int j = 0; j < 4; j++) {
                float2 f = __half22float2(hb[j]);
                ea += f.x * sw16[8 + 2 * j] + f.y * sw16[8 + 2 * j + 1];
            }
            int lo = 0, hi = NB;
            #pragma unroll
            for (int b = 0; b < 5; b++) {
                int mid = (lo + hi) >> 1;
                bool ge = (p >= s_off[mid]);
                lo = ge ? mid : lo;
                hi = ge ? hi : mid;
            }
            float lg = __ldg(&hs[sv]) + s_hd[lo] + ea;
            lg = lg > 0.f ? lg : 0.1f * lg;
            float ew = __expf(fminf(lg, 85.f));
            s_w[i] = ew;
            s_src[i] = sv;
            s_re[i * 2]     = ra;
            s_re[i * 2 + 1] = rb;
            atomicAdd(&s_sum[lo], ew);
        }
        __syncthreads();
        const __half* s_reh = (const __half*)s_re;
        #pragma unroll
        for (int j = 0; j < 4; j++) {
            int ndl = w * 4 + j;
            int lo = max(s_off[ndl], cs) - cs;
            int hi = min(s_off[ndl + 1], cs + cnt) - cs;
            #pragma unroll 4
            for (int i = lo; i < hi; i++) {
                float wv = s_w[i];
                int sv = s_src[i];
                float2 hp = __half22float2(h16[(size_t)sv * 32 + lane]);
                acc[j][0] += wv * hp.x;
                acc[j][1] += wv * hp.y;
                if (lane < ED)
                    acc16[j] += wv * __half2float(s_reh[i * ED + lane]);
            }
        }
        __syncthreads();
    }
    #pragma unroll
    for (int j = 0; j < 4; j++) {
        int ndl = w * 4 + j;
        int nd = node0 + ndl;
        float a0 = acc[j][0], a1 = acc[j][1];
        #pragma unroll
        for (int k = 0; k < ED; k++) {
            float b = __shfl_sync(0xffffffffu, acc16[j], k);
            a0 += b * sWe[k * H + 2 * lane];
            a1 += b * sWe[k * H + 2 * lane + 1];
        }
        if (nd < n) {
            float s = s_sum[ndl];
            float inv = (s > 0.f) ? (1.0f / s) : 0.f;
            agg16[(size_t)nd * 32 + lane] = __floats2half2_rn(a0 * inv, a1 * inv);
        }
    }
}

// ---------------- fused pool + interaction + MLP readout (h16 input) --------
__global__ void __launch_bounds__(256)
poolmlp_kernel(const int* __restrict__ goff, const float* __restrict__ d_edge,
               const float* __restrict__ w_d, const float* __restrict__ b_d,
               const float* __restrict__ i_node, const float* __restrict__ W_i,
               const __half2* __restrict__ h16,
               const float* __restrict__ W_mlp, const float* __restrict__ b_mlp,
               const float* __restrict__ W_out, const float* __restrict__ b_out,
               float* __restrict__ out, int g_total) {
    __shared__ float sW[3 * 4096];
    __shared__ float sb[3 * 64];
    __shared__ float sWo[64];
    __shared__ float sx[8][64];
    int tid = threadIdx.x, lane = tid & 31, wl = tid >> 5;
    for (int i = tid; i < 3 * 4096; i += 256) sW[i] = W_mlp[i];
    if (tid < 192) sb[tid] = b_mlp[tid];
    if (tid < 64) sWo[tid] = W_out[tid];
    __syncthreads();
    float wd = w_d[0], bd = b_d[0], bo = b_out[0];
    int g = blockIdx.x * 8 + wl;
    if (g >= g_total) return;

    int beg = goff[g], end = goff[g + 1];
    float s00 = 0.f, s01 = 0.f, s10 = 0.f, s11 = 0.f, sg = 0.f;
    for (int nn = beg; nn < end; nn++) {
        float gate = 1.0f / (1.0f + __expf(-(d_edge[nn] * wd + bd)));
        float2 hp = __half22float2(h16[(size_t)nn * 32 + lane]);
        s00 += hp.x; s01 += hp.y;
        s10 += gate * hp.x; s11 += gate * hp.y;
        sg += gate;
    }
    float iv = i_node[g];
    float hi0 = iv * W_i[2 * lane] + s10;
    float hi1 = iv * W_i[2 * lane + 1] + s11;
    sx[wl][2 * lane]     = s00 + sg * hi0;
    sx[wl][2 * lane + 1] = s01 + sg * hi1;
    __syncwarp();

    for (int l = 0; l < 3; l++) {
        float a0 = sb[l * 64 + 2 * lane];
        float a1 = sb[l * 64 + 2 * lane + 1];
        const float* Wl = sW + l * 4096;
        #pragma unroll 8
        for (int k = 0; k < 64; k++) {
            float xv = sx[wl][k];
            a0 += xv * Wl[k * 64 + 2 * lane];
            a1 += xv * Wl[k * 64 + 2 * lane + 1];
        }
        a0 = fmaxf(a0, 0.f);
        a1 = fmaxf(a1, 0.f);
        __syncwarp();
        sx[wl][2 * lane]     = a0;
        sx[wl][2 * lane + 1] = a1;
        __syncwarp();
    }
    float part = sx[wl][2 * lane] * sWo[2 * lane] + sx[wl][2 * lane + 1] * sWo[2 * lane + 1];
    #pragma unroll
    for (int d = 16; d; d >>= 1) part += __shfl_xor_sync(0xffffffffu, part, d);
    if (lane == 0) out[g] = part + bo;
}

// ---------------- launcher ----------------
extern "C" void kernel_launch(void* const* d_in, const int* in_sizes, int n_in,
                              void* d_out, int out_size) {
    const float* r_node  = (const float*)d_in[0];
    const float* i_node  = (const float*)d_in[1];
    const float* r_edge  = (const float*)d_in[2];
    const float* d_edge  = (const float*)d_in[3];
    const int*   r2r_src = (const int*)d_in[4];
    const int*   r2r_dst = (const int*)d_in[5];
    const int*   graph_id= (const int*)d_in[6];
    const float* W_r     = (const float*)d_in[7];
    const float* W_i     = (const float*)d_in[8];
    const float* W_e     = (const float*)d_in[9];
    const float* Wm      = (const float*)d_in[10];
    const float* a_s     = (const float*)d_in[11];
    const float* a_d     = (const float*)d_in[12];
    const float* a_e     = (const float*)d_in[13];
    const float* w_d     = (const float*)d_in[14];
    const float* b_d     = (const float*)d_in[15];
    const float* W_mlp   = (const float*)d_in[16];
    const float* b_mlp   = (const float*)d_in[17];
    const float* W_out   = (const float*)d_in[18];
    const float* b_out   = (const float*)d_in[19];
    float* out = (float*)d_out;

    const int nN = in_sizes[3];
    const int nE = in_sizes[4];
    const int nG = in_sizes[1];

    float *p_h, *p_hs, *p_hd;
    __half2 *p_h16, *p_agg16;
    uint4*   p_recsr;
    int *p_deg, *p_off, *p_cur, *p_srcs, *p_perm, *p_gcnt, *p_goff, *p_bsums;
    cudaGetSymbolAddress((void**)&p_h, g_h);
    cudaGetSymbolAddress((void**)&p_h16, g_h16);
    cudaGetSymbolAddress((void**)&p_agg16, g_agg16);
    cudaGetSymbolAddress((void**)&p_hs, g_hs);
    cudaGetSymbolAddress((void**)&p_hd, g_hd);
    cudaGetSymbolAddress((void**)&p_recsr, g_recsr);
    cudaGetSymbolAddress((void**)&p_deg, g_deg);
    cudaGetSymbolAddress((void**)&p_off, g_off);
    cudaGetSymbolAddress((void**)&p_cur, g_cur);
    cudaGetSymbolAddress((void**)&p_srcs, g_srcs);
    cudaGetSymbolAddress((void**)&p_perm, g_perm);
    cudaGetSymbolAddress((void**)&p_gcnt, g_gcnt);
    cudaGetSymbolAddress((void**)&p_goff, g_goff);
    cudaGetSymbolAddress((void**)&p_bsums, g_bsums);

    int nbN = (nN + 1023) / 1024;
    int nbG = (nG + 1023) / 1024;
    int layer_blocks = (nN + NB - 1) / NB;

    // 0: zero, 1: hist, 2: scanN, 3: gemm64 (ncu window)
    zero_fused<<<(nN + 255) / 256, 256>>>(p_deg, p_cur, p_gcnt, nN, nG);
    hist_fused<<<(nE + 255) / 256, 256>>>(r2r_dst, graph_id, p_deg, p_gcnt, nE, nN);
    scan_block<<<nbN, 1024>>>(p_deg, p_off, p_bsums, nN);
    gemm64_kernel<<<592, 256>>>(r_node, nullptr, W_r, nullptr, p_h, p_h16,
                                a_s, a_d, p_hs, p_hd, nN, 0);
    scan_sums_par<<<1, 128>>>(p_bsums, nbN);
    add_base<<<nbN, 1024>>>(p_off, p_bsums, nN);
    scan_block<<<nbG, 1024>>>(p_gcnt, p_goff, p_bsums, nG);
    scan_sums_par<<<1, 128>>>(p_bsums, nbG);
    add_base<<<nbG, 1024>>>(p_goff, p_bsums, nG);
    scatter_kernel<<<(nE + 255) / 256, 256>>>(r2r_src, r2r_dst, p_off, p_cur,
                                              p_perm, p_srcs, nE);
    build_recsr_kernel<<<(nE + 255) / 256, 256>>>(r_edge, p_perm, p_recsr, nE);

    // --- 4 attention conv layers ---
    for (int l = 0; l < LYR; l++) {
        layer_kernel<<<layer_blocks, 256>>>(p_off, p_srcs, p_recsr, W_e, a_e, l,
                                            p_hs, p_hd, p_h16, p_agg16, nN);
        const float* as_next = (l < LYR - 1) ? (a_s + (l + 1) * H) : nullptr;
        const float* ad_next = (l < LYR - 1) ? (a_d + (l + 1) * H) : nullptr;
        gemm64_kernel<<<592, 256>>>(nullptr, p_agg16, Wm + (size_t)l * H * H,
                                    p_h, p_h, p_h16,
                                    as_next, ad_next, p_hs, p_hd, nN, 1);
    }

    // --- fused pool + interaction + MLP ---
    poolmlp_kernel<<<(nG + 7) / 8, 256>>>(p_goff, d_edge, w_d, b_d, i_node, W_i,
                                          p_h16, W_mlp, b_mlp, W_out, b_out, out, nG);
}